// round 4
// baseline (speedup 1.0000x reference)
#include <cuda_runtime.h>
#include <math.h>

// FactorPredictor: N=200000 stocks, D=512, H=256, K=64 heads.
// Pipeline: prep (qWk, q.bk) -> score GEMM + exp + partial sums
//           -> pooled GEMM (split-N partials) -> reduce -> head projection.
// All fp32; inner GEMMs use packed fma.rn.f32x2 (sm_100+) for 2x FFMA rate.

#define NN 200000
#define DD 512
#define HH 256
#define KK 64
#define SCALE 0.0625f        // 1/sqrt(256)
#define NT 782               // ceil(NN/256)
#define SGRID 296
#define NSLICE 37
#define SLICE 5408           // 37*5408 >= NN, multiple of 32

// ---- scratch (no allocations allowed) ----
__device__ __align__(256) float g_qWkT[DD * KK];                  // [d][k]
__device__ __align__(256) float g_qbk[KK];
__device__ __align__(256) float g_sumpart[SGRID * KK];
__device__ __align__(256) float g_P[(size_t)NN * KK];             // exp(score), [n][k]
__device__ __align__(256) float g_part[148 * KK * 128];
__device__ __align__(256) float g_pooled[KK * DD];

// ---- f32x2 helpers ----
__device__ __forceinline__ void fma2(unsigned long long &c, unsigned long long a,
                                     unsigned long long b) {
    asm("fma.rn.f32x2 %0, %1, %2, %0;" : "+l"(c) : "l"(a), "l"(b));
}
__device__ __forceinline__ unsigned long long pk2(float lo, float hi) {
    unsigned long long r;
    asm("mov.b64 %0, {%1, %2};" : "=l"(r) : "f"(lo), "f"(hi));
    return r;
}
__device__ __forceinline__ float2 upk2(unsigned long long v) {
    float2 r;
    asm("mov.b64 {%0, %1}, %2;" : "=f"(r.x), "=f"(r.y) : "l"(v));
    return r;
}

// ---- K0: qWkT[d][k] = sum_h q[k,h]*Wk[k,h,d]; qbk[k] = q[k,:].bk[k,:] ----
__global__ __launch_bounds__(512) void prep_kernel(const float* __restrict__ q,
                                                   const float* __restrict__ Wk,
                                                   const float* __restrict__ bk) {
    const int k = blockIdx.x, t = threadIdx.x;
    __shared__ float qs[HH];
    __shared__ float red[256];
    if (t < HH) qs[t] = q[k * HH + t];
    __syncthreads();
    const float* w = Wk + (size_t)k * HH * DD + t;
    float acc = 0.f;
#pragma unroll 8
    for (int h = 0; h < HH; h++) acc += qs[h] * w[(size_t)h * DD];
    g_qWkT[t * KK + k] = acc;
    if (t < HH) red[t] = qs[t] * bk[k * HH + t];
    __syncthreads();
    for (int o = 128; o > 0; o >>= 1) {
        if (t < o) red[t] += red[t + o];
        __syncthreads();
    }
    if (t == 0) g_qbk[k] = red[0];
}

// ---- K1: scores = qWk @ e^T; P = exp((s+qbk)*SCALE); per-block k-sums ----
// Tile 64k x 256n per iteration, d-chunks of 32. 256 thr, thread tile 8k x 8n.
__global__ __launch_bounds__(256, 2) void score_kernel(const float* __restrict__ e) {
    __shared__ float As[32 * 64];
    __shared__ float Bs[32 * 260];
    const int t = threadIdx.x, tx = t & 31, ty = t >> 5;
    float qb[8];
#pragma unroll
    for (int kk = 0; kk < 8; kk++) qb[kk] = g_qbk[ty * 8 + kk];
    float sumacc[8] = {0.f, 0.f, 0.f, 0.f, 0.f, 0.f, 0.f, 0.f};

    for (int tile = blockIdx.x; tile < NT; tile += gridDim.x) {
        const int n0 = tile * 256;
        unsigned long long acc[8][4];
#pragma unroll
        for (int a = 0; a < 8; a++)
#pragma unroll
            for (int b = 0; b < 4; b++) acc[a][b] = 0ull;

        for (int d0 = 0; d0 < DD; d0 += 32) {
            __syncthreads();
#pragma unroll
            for (int j = 0; j < 8; j++)
                As[t + j * 256] = g_qWkT[d0 * 64 + t + j * 256];
#pragma unroll
            for (int j = 0; j < 8; j++) {
                int f = t + j * 256;
                int nn = f >> 3, fq = f & 7;
                int n = n0 + nn;
                float4 v = make_float4(0.f, 0.f, 0.f, 0.f);
                if (n < NN) v = *(const float4*)(e + (size_t)n * DD + d0 + fq * 4);
                Bs[(fq * 4 + 0) * 260 + nn] = v.x;
                Bs[(fq * 4 + 1) * 260 + nn] = v.y;
                Bs[(fq * 4 + 2) * 260 + nn] = v.z;
                Bs[(fq * 4 + 3) * 260 + nn] = v.w;
            }
            __syncthreads();
#pragma unroll
            for (int dc = 0; dc < 32; dc++) {
                float4 a0 = *(const float4*)(As + dc * 64 + ty * 8);
                float4 a1 = *(const float4*)(As + dc * 64 + ty * 8 + 4);
                float4 b0 = *(const float4*)(Bs + dc * 260 + tx * 4);
                float4 b1 = *(const float4*)(Bs + dc * 260 + 128 + tx * 4);
                unsigned long long bp0 = pk2(b0.x, b0.y), bp1 = pk2(b0.z, b0.w);
                unsigned long long bp2 = pk2(b1.x, b1.y), bp3 = pk2(b1.z, b1.w);
                float av[8] = {a0.x, a0.y, a0.z, a0.w, a1.x, a1.y, a1.z, a1.w};
#pragma unroll
                for (int kk = 0; kk < 8; kk++) {
                    unsigned long long ap = pk2(av[kk], av[kk]);
                    fma2(acc[kk][0], ap, bp0);
                    fma2(acc[kk][1], ap, bp1);
                    fma2(acc[kk][2], ap, bp2);
                    fma2(acc[kk][3], ap, bp3);
                }
            }
        }
        // epilogue: exp, store P (n-major), accumulate sums
        float pv[8][8];
#pragma unroll
        for (int kk = 0; kk < 8; kk++) {
            float2 v;
            v = upk2(acc[kk][0]); pv[0][kk] = v.x; pv[1][kk] = v.y;
            v = upk2(acc[kk][1]); pv[2][kk] = v.x; pv[3][kk] = v.y;
            v = upk2(acc[kk][2]); pv[4][kk] = v.x; pv[5][kk] = v.y;
            v = upk2(acc[kk][3]); pv[6][kk] = v.x; pv[7][kk] = v.y;
        }
#pragma unroll
        for (int j = 0; j < 8; j++) {
            int n = n0 + (j < 4 ? tx * 4 + j : 128 + tx * 4 + (j - 4));
            if (n < NN) {
#pragma unroll
                for (int kk = 0; kk < 8; kk++) {
                    float p = __expf((pv[j][kk] + qb[kk]) * SCALE);
                    pv[j][kk] = p;
                    sumacc[kk] += p;
                }
                *(float4*)(g_P + (size_t)n * 64 + ty * 8) =
                    make_float4(pv[j][0], pv[j][1], pv[j][2], pv[j][3]);
                *(float4*)(g_P + (size_t)n * 64 + ty * 8 + 4) =
                    make_float4(pv[j][4], pv[j][5], pv[j][6], pv[j][7]);
            }
        }
    }
#pragma unroll
    for (int kk = 0; kk < 8; kk++) {
        float s = sumacc[kk];
#pragma unroll
        for (int o = 16; o > 0; o >>= 1) s += __shfl_xor_sync(0xffffffffu, s, o);
        if (tx == 0) g_sumpart[blockIdx.x * 64 + ty * 8 + kk] = s;
    }
}

// ---- K2: partial pooled[k][d] = sum_{n in slice} P[n][k]*e[n][d] ----
// grid = 4 d-chunks x 37 n-slices. 256 thr, C tile 64k x 128d, thread 8k x 4d.
__global__ __launch_bounds__(256, 2) void pool_kernel(const float* __restrict__ e) {
    __shared__ float Ps[32 * 64];
    __shared__ float Es[32 * 128];
    const int t = threadIdx.x, tx = t & 31, ty = t >> 5;
    const int d0 = (blockIdx.x & 3) * 128;
    const int nbeg = (blockIdx.x >> 2) * SLICE;
    const int nend = (nbeg + SLICE < NN) ? nbeg + SLICE : NN;

    unsigned long long acc[8][2];
#pragma unroll
    for (int a = 0; a < 8; a++) { acc[a][0] = 0ull; acc[a][1] = 0ull; }

    for (int n0 = nbeg; n0 < nend; n0 += 32) {
        __syncthreads();
#pragma unroll
        for (int j = 0; j < 2; j++) {
            int f = t + j * 256;
            int nn = f >> 4, kq = f & 15;
            int n = n0 + nn;
            float4 v = make_float4(0.f, 0.f, 0.f, 0.f);
            if (n < NN) v = *(const float4*)(g_P + (size_t)n * 64 + kq * 4);
            *(float4*)(Ps + nn * 64 + kq * 4) = v;
        }
#pragma unroll
        for (int j = 0; j < 4; j++) {
            int f = t + j * 256;
            int nn = f >> 5, dq = f & 31;
            int n = n0 + nn;
            float4 v = make_float4(0.f, 0.f, 0.f, 0.f);
            if (n < NN) v = *(const float4*)(e + (size_t)n * DD + d0 + dq * 4);
            *(float4*)(Es + nn * 128 + dq * 4) = v;
        }
        __syncthreads();
#pragma unroll
        for (int nn = 0; nn < 32; nn++) {
            float4 a0 = *(const float4*)(Ps + nn * 64 + ty * 8);
            float4 a1 = *(const float4*)(Ps + nn * 64 + ty * 8 + 4);
            float4 b  = *(const float4*)(Es + nn * 128 + tx * 4);
            unsigned long long bp0 = pk2(b.x, b.y), bp1 = pk2(b.z, b.w);
            float av[8] = {a0.x, a0.y, a0.z, a0.w, a1.x, a1.y, a1.z, a1.w};
#pragma unroll
            for (int kk = 0; kk < 8; kk++) {
                unsigned long long ap = pk2(av[kk], av[kk]);
                fma2(acc[kk][0], ap, bp0);
                fma2(acc[kk][1], ap, bp1);
            }
        }
    }
    float* dst = g_part + (size_t)blockIdx.x * (64 * 128);
#pragma unroll
    for (int kk = 0; kk < 8; kk++) {
        float2 v0 = upk2(acc[kk][0]), v1 = upk2(acc[kk][1]);
        *(float4*)(dst + (ty * 8 + kk) * 128 + tx * 4) =
            make_float4(v0.x, v0.y, v1.x, v1.y);
    }
}

// ---- K3: reduce split-N partials (deterministic order) ----
__global__ __launch_bounds__(512) void pool_reduce_kernel() {
    const int k = blockIdx.x, d = threadIdx.x;
    const int dq = d >> 7, dd = d & 127;
    float s = 0.f;
    for (int bs = 0; bs < NSLICE; bs++)
        s += g_part[(size_t)(bs * 4 + dq) * (64 * 128) + k * 128 + dd];
    g_pooled[k * DD + d] = s;
}

// ---- K4: normalize, Wv projection, mu/sigma ----
__global__ __launch_bounds__(256) void final_kernel(const float* __restrict__ Wv,
                                                    const float* __restrict__ bv,
                                                    const float* __restrict__ mu_w,
                                                    const float* __restrict__ mu_b,
                                                    const float* __restrict__ sigma_w,
                                                    const float* __restrict__ sigma_b,
                                                    float* __restrict__ out) {
    const int k = blockIdx.x, t = threadIdx.x;
    __shared__ float red[256];
    __shared__ float ps[DD];
    float s = 0.f;
    for (int b = t; b < SGRID; b += 256) s += g_sumpart[b * 64 + k];
    red[t] = s;
    __syncthreads();
    for (int o = 128; o > 0; o >>= 1) {
        if (t < o) red[t] += red[t + o];
        __syncthreads();
    }
    float inv = 1.f / red[0];
    for (int d = t; d < DD; d += 256) ps[d] = g_pooled[k * DD + d] * inv;
    __syncthreads();
    const float* wr = Wv + (size_t)k * HH * DD + (size_t)t * DD;
    float acc = 0.f;
    for (int d = 0; d < DD; d += 4) {
        float4 w = *(const float4*)(wr + d);
        acc += ps[d] * w.x + ps[d + 1] * w.y + ps[d + 2] * w.z + ps[d + 3] * w.w;
    }
    float h = acc + bv[k * HH + t];
    float m = h * mu_w[t];
    float g = h * sigma_w[t];
    __syncthreads();
    red[t] = m;
    __syncthreads();
    for (int o = 128; o > 0; o >>= 1) {
        if (t < o) red[t] += red[t + o];
        __syncthreads();
    }
    float mu = red[0] + mu_b[0];
    __syncthreads();
    red[t] = g;
    __syncthreads();
    for (int o = 128; o > 0; o >>= 1) {
        if (t < o) red[t] += red[t + o];
        __syncthreads();
    }
    if (t == 0) {
        out[k] = mu;
        out[KK + k] = expf(red[0] + sigma_b[0]);
    }
}

extern "C" void kernel_launch(void* const* d_in, const int* in_sizes, int n_in,
                              void* d_out, int out_size) {
    const float* e       = (const float*)d_in[0];
    const float* q       = (const float*)d_in[1];
    const float* Wk      = (const float*)d_in[2];
    const float* bk      = (const float*)d_in[3];
    const float* Wv      = (const float*)d_in[4];
    const float* bv      = (const float*)d_in[5];
    const float* mu_w    = (const float*)d_in[6];
    const float* mu_b    = (const float*)d_in[7];
    const float* sigma_w = (const float*)d_in[8];
    const float* sigma_b = (const float*)d_in[9];
    float* out = (float*)d_out;

    prep_kernel<<<KK, 512>>>(q, Wk, bk);
    score_kernel<<<SGRID, 256>>>(e);
    pool_kernel<<<148, 256>>>(e);
    pool_reduce_kernel<<<KK, 512>>>();
    final_kernel<<<KK, 256>>>(Wv, bv, mu_w, mu_b, sigma_w, sigma_b, out);
}